// round 14
// baseline (speedup 1.0000x reference)
#include <cuda_runtime.h>
#include <cstdint>

// B=4, H=16, S=1024, D=64 ; out = [O (64*1024*64 f32)] ++ [attn (64*1024*1024 f32)]
#define SQ 1024
#define DD 64
#define QT 32
#define NBH 64
#define QP 36            // u32 (bf16x2) row stride for packed K/Q planes
#define OS 68            // O-reduction plane row stride (f32)
#define KHPX (256*QP)    // u32 offset of lo plane within a 256-key K buffer
#define KBUFX (2*KHPX)   // u32 per 256-key K buffer (hi+lo planes)
#define VPS 136          // u32 row stride of interleaved V plane (64 pairs x {hi,lo} + pad)
#define VPBUF (64*VPS)   // u32 per V plane buffer (64 d-rows) = 8704

__device__ __forceinline__ uint32_t packbf(float lo, float hi) {
    uint32_t r;
    asm("cvt.rn.bf16x2.f32 %0, %1, %2;" : "=r"(r) : "f"(hi), "f"(lo));
    return r;
}
__device__ __forceinline__ float bf_lo(uint32_t p) { return __uint_as_float(p << 16); }
__device__ __forceinline__ float bf_hi(uint32_t p) { return __uint_as_float(p & 0xffff0000u); }

__device__ __forceinline__ void mma16(float* c, uint32_t a0, uint32_t a1, uint32_t a2, uint32_t a3,
                                      uint32_t b0, uint32_t b1) {
    asm volatile("mma.sync.aligned.m16n8k16.row.col.f32.bf16.bf16.f32 "
                 "{%0,%1,%2,%3}, {%4,%5,%6,%7}, {%8,%9}, {%0,%1,%2,%3};\n"
                 : "+f"(c[0]), "+f"(c[1]), "+f"(c[2]), "+f"(c[3])
                 : "r"(a0), "r"(a1), "r"(a2), "r"(a3), "r"(b0), "r"(b1));
}

__global__ __launch_bounds__(512, 1)
void attn_bf16x3_vst_kernel(const float* __restrict__ Q,
                            const float* __restrict__ K,
                            const float* __restrict__ V,
                            const float* __restrict__ bias,
                            float* __restrict__ out)
{
    extern __shared__ uint32_t smu[];
    uint32_t* sQh  = smu;                          // 32*QP
    uint32_t* sQl  = sQh + QT * QP;                // 32*QP
    float*    sRed = (float*)(sQl + QT * QP);      // 32*8
    uint32_t* slab = (uint32_t*)(sRed + QT * 8);   // 2 * KBUFX (K bufs / V planes)
    float*    sOr  = (float*)(slab + 2 * KBUFX);   // 8 * 32 * OS

    const int t    = threadIdx.x;
    const int lane = t & 31;
    const int w    = t >> 5;
    const int qh   = w >> 3;             // 0..1 (q half)
    const int cg   = w & 7;              // 0..7 (column group)
    const int gid  = lane >> 2;
    const int tig  = lane & 3;
    const int rowA = qh * 16 + gid;

    const int bh = blockIdx.y;
    const int q0 = blockIdx.x * QT;

    const float* Qb = Q + ((size_t)bh * SQ + q0) * DD;
    const float* Kb = K + (size_t)bh * SQ * DD;
    const float* Vb = V + (size_t)bh * SQ * DD;
    float* outO = out + ((size_t)bh * SQ + q0) * DD;
    float* outA = out + (size_t)NBH * SQ * DD + ((size_t)bh * SQ + q0) * SQ;

    // ---- stage Q: packed bf16 hi/lo planes ----
    {
        int r = t >> 4, c4 = t & 15;
        float4 q = ((const float4*)Qb)[r * 16 + c4];
        uint32_t h0 = packbf(q.x, q.y), h1 = packbf(q.z, q.w);
        uint32_t l0 = packbf(q.x - bf_lo(h0), q.y - bf_hi(h0));
        uint32_t l1 = packbf(q.z - bf_lo(h1), q.w - bf_hi(h1));
        *(uint2*)&sQh[r * QP + c4 * 2] = make_uint2(h0, h1);
        *(uint2*)&sQl[r * QP + c4 * 2] = make_uint2(l0, l1);
    }

    float acc[16][4];
    #pragma unroll
    for (int j = 0; j < 16; j++) {
        acc[j][0] = 0.f; acc[j][1] = 0.f; acc[j][2] = 0.f; acc[j][3] = 0.f;
    }

    // ====== phase 1: scores = Q K^T (3xBF16 k16), 256-key chunks, 4 acc chains ======
    const int kkey = t >> 3, kdqa = t & 7;
    float4 ka, kb;

    #define LDK(chunk64) do {                                              \
        const float* _s = Kb + (size_t)(chunk64) * 64 * DD;                \
        ka = *(const float4*)(_s + kkey * DD + kdqa * 4);                  \
        kb = *(const float4*)(_s + kkey * DD + (kdqa + 8) * 4);            \
    } while (0)

    #define STK(bufp, sub) do {                                            \
        uint32_t* _h = (bufp);                                             \
        uint32_t* _l = (bufp) + KHPX;                                      \
        int _r = (sub) * 64 + kkey;                                        \
        uint32_t h0 = packbf(ka.x, ka.y), h1 = packbf(ka.z, ka.w);         \
        uint32_t l0 = packbf(ka.x - bf_lo(h0), ka.y - bf_hi(h0));          \
        uint32_t l1 = packbf(ka.z - bf_lo(h1), ka.w - bf_hi(h1));          \
        *(uint2*)&_h[_r * QP + kdqa * 2] = make_uint2(h0, h1);             \
        *(uint2*)&_l[_r * QP + kdqa * 2] = make_uint2(l0, l1);             \
        uint32_t h2 = packbf(kb.x, kb.y), h3 = packbf(kb.z, kb.w);         \
        uint32_t l2 = packbf(kb.x - bf_lo(h2), kb.y - bf_hi(h2));          \
        uint32_t l3 = packbf(kb.z - bf_lo(h3), kb.w - bf_hi(h3));         \
        *(uint2*)&_h[_r * QP + (kdqa + 8) * 2] = make_uint2(h2, h3);       \
        *(uint2*)&_l[_r * QP + (kdqa + 8) * 2] = make_uint2(l2, l3);       \
    } while (0)

    LDK(0); STK(slab, 0);
    LDK(1); STK(slab, 1);
    LDK(2); STK(slab, 2);
    LDK(3); STK(slab, 3);
    LDK(4);
    __syncthreads();

    #pragma unroll
    for (int c = 0; c < 4; c++) {
        uint32_t* bp = slab + (c & 1) * KBUFX;
        uint32_t* bq = slab + ((c + 1) & 1) * KBUFX;

        #pragma unroll
        for (int ds = 0; ds < 4; ds++) {
            const int p0 = ds * 8 + tig;
            uint32_t aH0 = sQh[rowA * QP + p0];
            uint32_t aH1 = sQh[(rowA + 8) * QP + p0];
            uint32_t aH2 = sQh[rowA * QP + p0 + 4];
            uint32_t aH3 = sQh[(rowA + 8) * QP + p0 + 4];
            uint32_t aL0 = sQl[rowA * QP + p0];
            uint32_t aL1 = sQl[(rowA + 8) * QP + p0];
            uint32_t aL2 = sQl[rowA * QP + p0 + 4];
            uint32_t aL3 = sQl[(rowA + 8) * QP + p0 + 4];

            #pragma unroll
            for (int sub = 0; sub < 4; sub++) {      // 4 independent acc chains
                const int row = sub * 64 + cg * 8 + gid;
                uint32_t bH0 = bp[row * QP + p0];
                uint32_t bH1 = bp[row * QP + p0 + 4];
                uint32_t bL0 = bp[KHPX + row * QP + p0];
                uint32_t bL1 = bp[KHPX + row * QP + p0 + 4];
                float* cc = acc[c * 4 + sub];
                mma16(cc, aH0, aH1, aH2, aH3, bH0, bH1);
                mma16(cc, aH0, aH1, aH2, aH3, bL0, bL1);
                mma16(cc, aL0, aL1, aL2, aL3, bH0, bH1);
            }
            if (c < 3) {
                STK(bq, ds);                          // stage sub ds of chunk c+1
                int ni = 4 * c + 5 + ds;
                if (ni < 16) LDK(ni);
            }
        }
        __syncthreads();
    }

    // ---- V chunk-0 LDG prefetch (overlaps softmax) ----
    const int kp = t & 63, dq8 = t >> 6;             // key pair 0..63, d-octet 0..7
    float4 v0a, v0b, v1a, v1b;
    #define LDV(chunk128) do {                                                     \
        const float* _s = Vb + ((size_t)(chunk128) * 128 + 2 * kp) * DD + dq8 * 8; \
        v0a = *(const float4*)_s;        v0b = *(const float4*)(_s + 4);           \
        v1a = *(const float4*)(_s + DD); v1b = *(const float4*)(_s + DD + 4);      \
    } while (0)
    #define STV(chunk) do {                                                        \
        uint32_t* _p = slab + (((chunk) & 1) ? VPBUF : 0);                         \
        float _ea[8] = {v0a.x, v0a.y, v0a.z, v0a.w, v0b.x, v0b.y, v0b.z, v0b.w};   \
        float _eb[8] = {v1a.x, v1a.y, v1a.z, v1a.w, v1b.x, v1b.y, v1b.z, v1b.w};   \
        _Pragma("unroll")                                                          \
        for (int _j = 0; _j < 8; _j++) {                                           \
            uint32_t _h = packbf(_ea[_j], _eb[_j]);                                \
            uint32_t _l = packbf(_ea[_j] - bf_lo(_h), _eb[_j] - bf_hi(_h));        \
            *(uint2*)&_p[(dq8 * 8 + _j) * VPS + kp * 2] = make_uint2(_h, _l);      \
        }                                                                          \
    } while (0)

    LDV(0);

    // ================= phase 2: scale + bias + softmax, attn write from regs =================
    const float scale = 0.125f;
    float m1 = -1e30f, m2 = -1e30f;
    #pragma unroll
    for (int j = 0; j < 16; j++) {
        const int col = j * 64 + cg * 8 + 2 * tig;
        float2 b1v = *(const float2*)&bias[(size_t)(q0 + rowA) * SQ + col];
        float2 b2v = *(const float2*)&bias[(size_t)(q0 + rowA + 8) * SQ + col];
        acc[j][0] = acc[j][0] * scale + b1v.x;
        acc[j][1] = acc[j][1] * scale + b1v.y;
        acc[j][2] = acc[j][2] * scale + b2v.x;
        acc[j][3] = acc[j][3] * scale + b2v.y;
        m1 = fmaxf(m1, fmaxf(acc[j][0], acc[j][1]));
        m2 = fmaxf(m2, fmaxf(acc[j][2], acc[j][3]));
    }
    m1 = fmaxf(m1, __shfl_xor_sync(0xffffffffu, m1, 1));
    m1 = fmaxf(m1, __shfl_xor_sync(0xffffffffu, m1, 2));
    m2 = fmaxf(m2, __shfl_xor_sync(0xffffffffu, m2, 1));
    m2 = fmaxf(m2, __shfl_xor_sync(0xffffffffu, m2, 2));
    if (tig == 0) {
        sRed[rowA * 8 + cg]       = m1;
        sRed[(rowA + 8) * 8 + cg] = m2;
    }
    __syncthreads();
    m1 = -1e30f; m2 = -1e30f;
    #pragma unroll
    for (int i = 0; i < 8; i++) {
        m1 = fmaxf(m1, sRed[rowA * 8 + i]);
        m2 = fmaxf(m2, sRed[(rowA + 8) * 8 + i]);
    }
    float s1 = 0.f, s2 = 0.f;
    #pragma unroll
    for (int j = 0; j < 16; j++) {
        acc[j][0] = __expf(acc[j][0] - m1);
        acc[j][1] = __expf(acc[j][1] - m1);
        acc[j][2] = __expf(acc[j][2] - m2);
        acc[j][3] = __expf(acc[j][3] - m2);
        s1 += acc[j][0] + acc[j][1];
        s2 += acc[j][2] + acc[j][3];
    }
    s1 += __shfl_xor_sync(0xffffffffu, s1, 1);
    s1 += __shfl_xor_sync(0xffffffffu, s1, 2);
    s2 += __shfl_xor_sync(0xffffffffu, s2, 1);
    s2 += __shfl_xor_sync(0xffffffffu, s2, 2);
    __syncthreads();
    if (tig == 0) {
        sRed[rowA * 8 + cg]       = s1;
        sRed[(rowA + 8) * 8 + cg] = s2;
    }
    __syncthreads();
    s1 = 0.f; s2 = 0.f;
    #pragma unroll
    for (int i = 0; i < 8; i++) {
        s1 += sRed[rowA * 8 + i];
        s2 += sRed[(rowA + 8) * 8 + i];
    }
    const float inv1 = 1.0f / s1;
    const float inv2 = 1.0f / s2;
    #pragma unroll
    for (int j = 0; j < 16; j++) {
        acc[j][0] *= inv1; acc[j][1] *= inv1;
        acc[j][2] *= inv2; acc[j][3] *= inv2;
        const int col = j * 64 + cg * 8 + 2 * tig;
        *(float2*)&outA[(size_t)rowA * SQ + col]       = make_float2(acc[j][0], acc[j][1]);
        *(float2*)&outA[(size_t)(rowA + 8) * SQ + col] = make_float2(acc[j][2], acc[j][3]);
    }

    // ============ phase 3: O = P V (3xBF16 k16), block-staged interleaved V planes ============
    float o[8][4];
    #pragma unroll
    for (int dt = 0; dt < 8; dt++) {
        o[dt][0] = 0.f; o[dt][1] = 0.f; o[dt][2] = 0.f; o[dt][3] = 0.f;
    }

    STV(0);            // chunk-0 planes (regs loaded pre-softmax)
    LDV(1);
    __syncthreads();

    #pragma unroll
    for (int c = 0; c < 8; c++) {
        const uint32_t* vp = slab + ((c & 1) ? VPBUF : 0);

        // A fragments (k16) straight from normalized acc
        uint32_t pH0 = packbf(acc[2 * c][0], acc[2 * c][1]);
        uint32_t pH1 = packbf(acc[2 * c][2], acc[2 * c][3]);
        uint32_t pH2 = packbf(acc[2 * c + 1][0], acc[2 * c + 1][1]);
        uint32_t pH3 = packbf(acc[2 * c + 1][2], acc[2 * c + 1][3]);
        uint32_t pL0 = packbf(acc[2 * c][0] - bf_lo(pH0), acc[2 * c][1] - bf_hi(pH0));
        uint32_t pL1 = packbf(acc[2 * c][2] - bf_lo(pH1), acc[2 * c][3] - bf_hi(pH1));
        uint32_t pL2 = packbf(acc[2 * c + 1][0] - bf_lo(pH2), acc[2 * c + 1][1] - bf_hi(pH2));
        uint32_t pL3 = packbf(acc[2 * c + 1][2] - bf_lo(pH3), acc[2 * c + 1][3] - bf_hi(pH3));

        #pragma unroll
        for (int dt = 0; dt < 8; dt++) {
            const uint32_t* row = vp + (dt * 8 + gid) * VPS;
            uint2 B0 = *(const uint2*)&row[(cg * 4 + tig) * 2];        // sub0 pair {hi,lo}
            uint2 B1 = *(const uint2*)&row[(32 + cg * 4 + tig) * 2];   // sub1 pair {hi,lo}
            mma16(o[dt], pH0, pH1, pH2, pH3, B0.x, B1.x);
            mma16(o[dt], pH0, pH1, pH2, pH3, B0.y, B1.y);
            mma16(o[dt], pL0, pL1, pL2, pL3, B0.x, B1.x);
        }

        if (c < 7) { STV(c + 1); if (c < 6) LDV(c + 2); }
        __syncthreads();   // publish chunk c+1 planes; retire chunk c readers
    }

    // ---- cross-cg reduction of partial O, then coalesced store ----
    {
        float* myp = sOr + cg * (32 * OS);
        #pragma unroll
        for (int dt = 0; dt < 8; dt++) {
            *(float2*)&myp[rowA * OS + dt * 8 + 2 * tig]       = make_float2(o[dt][0], o[dt][1]);
            *(float2*)&myp[(rowA + 8) * OS + dt * 8 + 2 * tig] = make_float2(o[dt][2], o[dt][3]);
        }
    }
    __syncthreads();
    {
        int r = t >> 4, c4 = t & 15;
        float4 s = make_float4(0.f, 0.f, 0.f, 0.f);
        #pragma unroll
        for (int p = 0; p < 8; p++) {
            float4 v = *(float4*)&sOr[p * (32 * OS) + r * OS + c4 * 4];
            s.x += v.x; s.y += v.y; s.z += v.z; s.w += v.w;
        }
        *(float4*)&outO[(size_t)r * DD + c4 * 4] = s;
    }
}

extern "C" void kernel_launch(void* const* d_in, const int* in_sizes, int n_in,
                              void* d_out, int out_size)
{
    const float* Q    = (const float*)d_in[0];
    const float* K    = (const float*)d_in[1];
    const float* V    = (const float*)d_in[2];
    const float* bias = (const float*)d_in[3];
    float* out        = (float*)d_out;

    const size_t smem_u32 = (size_t)(2 * QT * QP) + QT * 8 + 2 * KBUFX + 8 * 32 * OS;
    const size_t smem_bytes = smem_u32 * sizeof(uint32_t);   // 227,328 B
    cudaFuncSetAttribute(attn_bf16x3_vst_kernel,
                         cudaFuncAttributeMaxDynamicSharedMemorySize, (int)smem_bytes);

    dim3 grid(SQ / QT, NBH);
    attn_bf16x3_vst_kernel<<<grid, 512, smem_bytes>>>(Q, K, V, bias, out);
}

// round 15
// speedup vs baseline: 1.3762x; 1.3762x over previous
#include <cuda_runtime.h>
#include <cstdint>

// B=4, H=16, S=1024, D=64 ; out = [O (64*1024*64 f32)] ++ [attn (64*1024*1024 f32)]
#define SQ 1024
#define DD 64
#define QT 32
#define NBH 64
#define QPL 32            // u32 per swizzled plane row (128B = 64 bf16)
#define QPLANE (32*QPL)   // u32 per Q plane (32 rows)
#define KPL (256*QPL)     // u32 per K plane (256 keys)
#define KBUF2 (2*KPL)     // u32 per K buffer (hi+lo planes) = 16384
#define VRS 68            // raw V row stride (floats)
#define VBUF (128*VRS)    // f32 per raw V buffer (fits in KBUF2)
#define OS 68             // O-reduction plane row stride (f32)

__device__ __forceinline__ uint32_t packbf(float lo, float hi) {
    uint32_t r;
    asm("cvt.rn.bf16x2.f32 %0, %1, %2;" : "=r"(r) : "f"(hi), "f"(lo));
    return r;
}
__device__ __forceinline__ float bf_lo(uint32_t p) { return __uint_as_float(p << 16); }
__device__ __forceinline__ float bf_hi(uint32_t p) { return __uint_as_float(p & 0xffff0000u); }

__device__ __forceinline__ void mma16(float* c, uint32_t a0, uint32_t a1, uint32_t a2, uint32_t a3,
                                      uint32_t b0, uint32_t b1) {
    asm volatile("mma.sync.aligned.m16n8k16.row.col.f32.bf16.bf16.f32 "
                 "{%0,%1,%2,%3}, {%4,%5,%6,%7}, {%8,%9}, {%0,%1,%2,%3};\n"
                 : "+f"(c[0]), "+f"(c[1]), "+f"(c[2]), "+f"(c[3])
                 : "r"(a0), "r"(a1), "r"(a2), "r"(a3), "r"(b0), "r"(b1));
}
__device__ __forceinline__ void ldsm4(uint32_t& r0, uint32_t& r1, uint32_t& r2, uint32_t& r3,
                                      uint32_t addr) {
    asm volatile("ldmatrix.sync.aligned.m8n8.x4.shared.b16 {%0,%1,%2,%3}, [%4];"
                 : "=r"(r0), "=r"(r1), "=r"(r2), "=r"(r3) : "r"(addr));
}
__device__ __forceinline__ void cp16(uint32_t dst, const float* src) {
    asm volatile("cp.async.cg.shared.global [%0], [%1], 16;\n" :: "r"(dst), "l"(src));
}
__device__ __forceinline__ void cp_commit() {
    asm volatile("cp.async.commit_group;\n" ::: "memory");
}
template <int N>
__device__ __forceinline__ void cp_wait() {
    asm volatile("cp.async.wait_group %0;\n" :: "n"(N) : "memory");
}

__global__ __launch_bounds__(512, 1)
void attn_bf16x3_swz_kernel(const float* __restrict__ Q,
                            const float* __restrict__ K,
                            const float* __restrict__ V,
                            const float* __restrict__ bias,
                            float* __restrict__ out)
{
    extern __shared__ uint32_t smu[];
    uint32_t* sQh  = smu;                          // QPLANE (swizzled, 128B rows)
    uint32_t* sQl  = sQh + QPLANE;                 // QPLANE
    float*    sRed = (float*)(sQl + QPLANE);       // 32*8
    uint32_t* slab = (uint32_t*)(sRed + QT * 8);   // 2*KBUF2 (K swz planes / raw V)
    float*    sOr  = (float*)(slab + 2 * KBUF2);   // 8*32*OS

    const int t    = threadIdx.x;
    const int lane = t & 31;
    const int w    = t >> 5;
    const int qh   = w >> 3;             // 0..1 (q half)
    const int cg   = w & 7;              // 0..7 (column group)
    const int gid  = lane >> 2;
    const int tig  = lane & 3;
    const int rowA = qh * 16 + gid;

    const int bh = blockIdx.y;
    const int q0 = blockIdx.x * QT;

    const float* Qb = Q + ((size_t)bh * SQ + q0) * DD;
    const float* Kb = K + (size_t)bh * SQ * DD;
    const float* Vb = V + (size_t)bh * SQ * DD;
    float* outO = out + ((size_t)bh * SQ + q0) * DD;
    float* outA = out + (size_t)NBH * SQ * DD + ((size_t)bh * SQ + q0) * SQ;

    // ---- stage Q: swizzled 128B-row bf16 hi/lo planes (threads < 256) ----
    if (t < 256) {
        int r = t >> 3, dq8 = t & 7;
        const float* qr = Qb + r * DD + dq8 * 8;
        float4 qa = *(const float4*)qr;
        float4 qb = *(const float4*)(qr + 4);
        uint32_t h0 = packbf(qa.x, qa.y), h1 = packbf(qa.z, qa.w);
        uint32_t h2 = packbf(qb.x, qb.y), h3 = packbf(qb.z, qb.w);
        uint32_t l0 = packbf(qa.x - bf_lo(h0), qa.y - bf_hi(h0));
        uint32_t l1 = packbf(qa.z - bf_lo(h1), qa.w - bf_hi(h1));
        uint32_t l2 = packbf(qb.x - bf_lo(h2), qb.y - bf_hi(h2));
        uint32_t l3 = packbf(qb.z - bf_lo(h3), qb.w - bf_hi(h3));
        uint32_t off = r * QPL + (((dq8 * 16) ^ ((r & 7) << 4)) >> 2);
        *(uint4*)&sQh[off] = make_uint4(h0, h1, h2, h3);
        *(uint4*)&sQl[off] = make_uint4(l0, l1, l2, l3);
    }

    float acc[16][4];
    #pragma unroll
    for (int j = 0; j < 16; j++) {
        acc[j][0] = 0.f; acc[j][1] = 0.f; acc[j][2] = 0.f; acc[j][3] = 0.f;
    }

    // ====== phase 1: scores = Q K^T (3xBF16 k16), 256-key chunks, swizzled + ldmatrix ======
    const int kkey = t >> 3, kdq8 = t & 7;           // staging: key-in-group, d-octet
    const uint32_t kstXor = ((uint32_t)(kkey & 7)) << 4;
    float4 ka, kb;

    #define LDK(chunk64) do {                                              \
        const float* _s = Kb + ((size_t)(chunk64) * 64 + kkey) * DD + kdq8 * 8; \
        ka = *(const float4*)_s;                                           \
        kb = *(const float4*)(_s + 4);                                     \
    } while (0)

    #define STK(bufp, sub) do {                                            \
        int _row = (sub) * 64 + kkey;                                      \
        uint32_t _off = _row * QPL + (((kdq8 * 16) ^ kstXor) >> 2);        \
        uint32_t h0 = packbf(ka.x, ka.y), h1 = packbf(ka.z, ka.w);         \
        uint32_t h2 = packbf(kb.x, kb.y), h3 = packbf(kb.z, kb.w);         \
        uint32_t l0 = packbf(ka.x - bf_lo(h0), ka.y - bf_hi(h0));          \
        uint32_t l1 = packbf(ka.z - bf_lo(h1), ka.w - bf_hi(h1));          \
        uint32_t l2 = packbf(kb.x - bf_lo(h2), kb.y - bf_hi(h2));          \
        uint32_t l3 = packbf(kb.z - bf_lo(h3), kb.w - bf_hi(h3));          \
        *(uint4*)&(bufp)[_off] = make_uint4(h0, h1, h2, h3);               \
        *(uint4*)&(bufp)[KPL + _off] = make_uint4(l0, l1, l2, l3);         \
    } while (0)

    // ldmatrix lane address precompute
    const int g  = lane >> 3;
    const int l7 = lane & 7;
    const uint32_t sQhA  = (uint32_t)__cvta_generic_to_shared(sQh);
    const uint32_t slabA = (uint32_t)__cvta_generic_to_shared(slab);
    // A tiles: t0/t1 = (m0-7/m8-15, klo16B), t2/t3 = (m0-7/m8-15, khi16B)
    const int aRow = qh * 16 + (g & 1) * 8 + l7;
    const uint32_t aFixed = sQhA + (uint32_t)(aRow * 128);
    const uint32_t aKX  = (uint32_t)((g >> 1) * 16);
    const uint32_t aXor = ((uint32_t)(aRow & 7)) << 4;
    // B tiles per LDSM: t0/t1 = (subA, klo/khi), t2/t3 = (subB, klo/khi)
    const int bRow0 = ((g >> 1) + 0) * 64 + cg * 8 + l7;     // subs 0/1
    const int bRow1 = ((g >> 1) + 2) * 64 + cg * 8 + l7;     // subs 2/3
    const uint32_t bKX  = (uint32_t)((g & 1) * 16);
    const uint32_t bXor = ((uint32_t)l7) << 4;

    LDK(0); STK(slab, 0);
    LDK(1); STK(slab, 1);
    LDK(2); STK(slab, 2);
    LDK(3); STK(slab, 3);
    LDK(4);
    __syncthreads();

    #pragma unroll
    for (int c = 0; c < 4; c++) {
        const uint32_t kbase = slabA + (uint32_t)((c & 1) * (KBUF2 * 4));
        uint32_t* bq = slab + ((c + 1) & 1) * KBUF2;

        #pragma unroll
        for (int ds = 0; ds < 4; ds++) {
            const uint32_t at = (uint32_t)(ds * 32 + aKX) ^ aXor;
            const uint32_t bt = (uint32_t)(ds * 32 + bKX) ^ bXor;
            uint32_t aH0, aH1, aH2, aH3, aL0, aL1, aL2, aL3;
            ldsm4(aH0, aH1, aH2, aH3, aFixed + at);
            ldsm4(aL0, aL1, aL2, aL3, aFixed + at + QPLANE * 4);
            uint32_t bh01_0, bh01_1, bh01_2, bh01_3;   // b0,b1 of sub0 ; b0,b1 of sub1
            uint32_t bh23_0, bh23_1, bh23_2, bh23_3;   // subs 2,3
            uint32_t bl01_0, bl01_1, bl01_2, bl01_3;
            uint32_t bl23_0, bl23_1, bl23_2, bl23_3;
            ldsm4(bh01_0, bh01_1, bh01_2, bh01_3, kbase + (uint32_t)(bRow0 * 128) + bt);
            ldsm4(bh23_0, bh23_1, bh23_2, bh23_3, kbase + (uint32_t)(bRow1 * 128) + bt);
            ldsm4(bl01_0, bl01_1, bl01_2, bl01_3, kbase + (uint32_t)(bRow0 * 128) + bt + KPL * 4);
            ldsm4(bl23_0, bl23_1, bl23_2, bl23_3, kbase + (uint32_t)(bRow1 * 128) + bt + KPL * 4);

            float* c0 = acc[c * 4 + 0];
            float* c1 = acc[c * 4 + 1];
            float* c2 = acc[c * 4 + 2];
            float* c3 = acc[c * 4 + 3];
            mma16(c0, aH0, aH1, aH2, aH3, bh01_0, bh01_1);
            mma16(c1, aH0, aH1, aH2, aH3, bh01_2, bh01_3);
            mma16(c2, aH0, aH1, aH2, aH3, bh23_0, bh23_1);
            mma16(c3, aH0, aH1, aH2, aH3, bh23_2, bh23_3);
            mma16(c0, aH0, aH1, aH2, aH3, bl01_0, bl01_1);
            mma16(c1, aH0, aH1, aH2, aH3, bl01_2, bl01_3);
            mma16(c2, aH0, aH1, aH2, aH3, bl23_0, bl23_1);
            mma16(c3, aH0, aH1, aH2, aH3, bl23_2, bl23_3);
            mma16(c0, aL0, aL1, aL2, aL3, bh01_0, bh01_1);
            mma16(c1, aL0, aL1, aL2, aL3, bh01_2, bh01_3);
            mma16(c2, aL0, aL1, aL2, aL3, bh23_0, bh23_1);
            mma16(c3, aL0, aL1, aL2, aL3, bh23_2, bh23_3);

            if (c < 3) {
                STK(bq, ds);
                int ni = 4 * c + 5 + ds;
                if (ni < 16) LDK(ni);
            }
        }
        __syncthreads();
    }

    // ---- kick off V chunk 0 (raw f32, cp.async) into slab — overlaps softmax ----
    float* vb0 = (float*)slab;
    float* vb1 = (float*)(slab + KBUF2);
    {
        uint32_t dst = (uint32_t)__cvta_generic_to_shared(vb0);
        #pragma unroll
        for (int n = 0; n < 4; n++) {
            int i = t + n * 512; int key = i >> 4, c16 = i & 15;
            cp16(dst + (uint32_t)(key * VRS + c16 * 4) * 4, Vb + key * DD + c16 * 4);
        }
        cp_commit();
    }

    // ================= phase 2: scale + bias + softmax, attn write from regs =================
    const float scale = 0.125f;
    float m1 = -1e30f, m2 = -1e30f;
    #pragma unroll
    for (int j = 0; j < 16; j++) {
        const int col = j * 64 + cg * 8 + 2 * tig;
        float2 b1v = *(const float2*)&bias[(size_t)(q0 + rowA) * SQ + col];
        float2 b2v = *(const float2*)&bias[(size_t)(q0 + rowA + 8) * SQ + col];
        acc[j][0] = acc[j][0] * scale + b1v.x;
        acc[j][1] = acc[j][1] * scale + b1v.y;
        acc[j][2] = acc[j][2] * scale + b2v.x;
        acc[j][3] = acc[j][3] * scale + b2v.y;
        m1 = fmaxf(m1, fmaxf(acc[j][0], acc[j][1]));
        m2 = fmaxf(m2, fmaxf(acc[j][2], acc[j][3]));
    }
    m1 = fmaxf(m1, __shfl_xor_sync(0xffffffffu, m1, 1));
    m1 = fmaxf(m1, __shfl_xor_sync(0xffffffffu, m1, 2));
    m2 = fmaxf(m2, __shfl_xor_sync(0xffffffffu, m2, 1));
    m2 = fmaxf(m2, __shfl_xor_sync(0xffffffffu, m2, 2));
    if (tig == 0) {
        sRed[rowA * 8 + cg]       = m1;
        sRed[(rowA + 8) * 8 + cg] = m2;
    }
    __syncthreads();
    m1 = -1e30f; m2 = -1e30f;
    #pragma unroll
    for (int i = 0; i < 8; i++) {
        m1 = fmaxf(m1, sRed[rowA * 8 + i]);
        m2 = fmaxf(m2, sRed[(rowA + 8) * 8 + i]);
    }
    float s1 = 0.f, s2 = 0.f;
    #pragma unroll
    for (int j = 0; j < 16; j++) {
        acc[j][0] = __expf(acc[j][0] - m1);
        acc[j][1] = __expf(acc[j][1] - m1);
        acc[j][2] = __expf(acc[j][2] - m2);
        acc[j][3] = __expf(acc[j][3] - m2);
        s1 += acc[j][0] + acc[j][1];
        s2 += acc[j][2] + acc[j][3];
    }
    s1 += __shfl_xor_sync(0xffffffffu, s1, 1);
    s1 += __shfl_xor_sync(0xffffffffu, s1, 2);
    s2 += __shfl_xor_sync(0xffffffffu, s2, 1);
    s2 += __shfl_xor_sync(0xffffffffu, s2, 2);
    __syncthreads();
    if (tig == 0) {
        sRed[rowA * 8 + cg]       = s1;
        sRed[(rowA + 8) * 8 + cg] = s2;
    }
    __syncthreads();
    s1 = 0.f; s2 = 0.f;
    #pragma unroll
    for (int i = 0; i < 8; i++) {
        s1 += sRed[rowA * 8 + i];
        s2 += sRed[(rowA + 8) * 8 + i];
    }
    const float inv1 = 1.0f / s1;
    const float inv2 = 1.0f / s2;
    #pragma unroll
    for (int j = 0; j < 16; j++) {
        acc[j][0] *= inv1; acc[j][1] *= inv1;
        acc[j][2] *= inv2; acc[j][3] *= inv2;
        const int col = j * 64 + cg * 8 + 2 * tig;
        *(float2*)&outA[(size_t)rowA * SQ + col]       = make_float2(acc[j][0], acc[j][1]);
        *(float2*)&outA[(size_t)(rowA + 8) * SQ + col] = make_float2(acc[j][2], acc[j][3]);
    }

    // ============ phase 3: O = P V (3xBF16 k16), raw-V cp.async, inline convert (R13) ============
    float o[8][4];
    #pragma unroll
    for (int dt = 0; dt < 8; dt++) {
        o[dt][0] = 0.f; o[dt][1] = 0.f; o[dt][2] = 0.f; o[dt][3] = 0.f;
    }

    #pragma unroll
    for (int c = 0; c < 8; c++) {
        if (c > 0) __syncthreads();           // prior readers of target buffer done
        if (c < 7) {
            float* nb = ((c + 1) & 1) ? vb1 : vb0;
            uint32_t dst = (uint32_t)__cvta_generic_to_shared(nb);
            const float* src = Vb + (size_t)(c + 1) * 128 * DD;
            #pragma unroll
            for (int n = 0; n < 4; n++) {
                int i = t + n * 512; int key = i >> 4, c16 = i & 15;
                cp16(dst + (uint32_t)(key * VRS + c16 * 4) * 4, src + key * DD + c16 * 4);
            }
            cp_commit();
            cp_wait<1>();
        } else {
            cp_wait<0>();
        }
        __syncthreads();                      // chunk c visible to all
        const float* vb = (c & 1) ? vb1 : vb0;

        uint32_t pH0 = packbf(acc[2 * c][0], acc[2 * c][1]);
        uint32_t pH1 = packbf(acc[2 * c][2], acc[2 * c][3]);
        uint32_t pH2 = packbf(acc[2 * c + 1][0], acc[2 * c + 1][1]);
        uint32_t pH3 = packbf(acc[2 * c + 1][2], acc[2 * c + 1][3]);
        uint32_t pL0 = packbf(acc[2 * c][0] - bf_lo(pH0), acc[2 * c][1] - bf_hi(pH0));
        uint32_t pL1 = packbf(acc[2 * c][2] - bf_lo(pH1), acc[2 * c][3] - bf_hi(pH1));
        uint32_t pL2 = packbf(acc[2 * c + 1][0] - bf_lo(pH2), acc[2 * c + 1][1] - bf_hi(pH2));
        uint32_t pL3 = packbf(acc[2 * c + 1][2] - bf_lo(pH3), acc[2 * c + 1][3] - bf_hi(pH3));

        const float* r0 = vb + (size_t)(cg * 8 + 2 * tig) * VRS;
        const float* r1 = r0 + VRS;
        const float* r2 = vb + (size_t)(64 + cg * 8 + 2 * tig) * VRS;
        const float* r3 = r2 + VRS;

        #pragma unroll
        for (int dt = 0; dt < 8; dt++) {
            float va = r0[dt * 8 + gid];
            float vx = r1[dt * 8 + gid];
            uint32_t b0H = packbf(va, vx);
            uint32_t b0L = packbf(va - bf_lo(b0H), vx - bf_hi(b0H));
            float wa = r2[dt * 8 + gid];
            float wx = r3[dt * 8 + gid];
            uint32_t b1H = packbf(wa, wx);
            uint32_t b1L = packbf(wa - bf_lo(b1H), wx - bf_hi(b1H));
            mma16(o[dt], pH0, pH1, pH2, pH3, b0H, b1H);
            mma16(o[dt], pH0, pH1, pH2, pH3, b0L, b1L);
            mma16(o[dt], pL0, pL1, pL2, pL3, b0H, b1H);
        }
    }

    // ---- cross-cg reduction of partial O, then coalesced store ----
    __syncthreads();
    {
        float* myp = sOr + cg * (32 * OS);
        #pragma unroll
        for (int dt = 0; dt < 8; dt++) {
            *(float2*)&myp[rowA * OS + dt * 8 + 2 * tig]       = make_float2(o[dt][0], o[dt][1]);
            *(float2*)&myp[(rowA + 8) * OS + dt * 8 + 2 * tig] = make_float2(o[dt][2], o[dt][3]);
        }
    }
    __syncthreads();
    {
        int r = t >> 4, c4 = t & 15;
        float4 s = make_float4(0.f, 0.f, 0.f, 0.f);
        #pragma unroll
        for (int p = 0; p < 8; p++) {
            float4 v = *(float4*)&sOr[p * (32 * OS) + r * OS + c4 * 4];
            s.x += v.x; s.y += v.y; s.z += v.z; s.w += v.w;
        }
        *(float4*)&outO[(size_t)r * DD + c4 * 4] = s;
    }
}

extern "C" void kernel_launch(void* const* d_in, const int* in_sizes, int n_in,
                              void* d_out, int out_size)
{
    const float* Q    = (const float*)d_in[0];
    const float* K    = (const float*)d_in[1];
    const float* V    = (const float*)d_in[2];
    const float* bias = (const float*)d_in[3];
    float* out        = (float*)d_out;

    const size_t smem_u32 = (size_t)(2 * QPLANE) + QT * 8 + 2 * KBUF2 + 8 * 32 * OS;
    const size_t smem_bytes = smem_u32 * sizeof(uint32_t);   // 209,920 B
    cudaFuncSetAttribute(attn_bf16x3_swz_kernel,
                         cudaFuncAttributeMaxDynamicSharedMemorySize, (int)smem_bytes);

    dim3 grid(SQ / QT, NBH);
    attn_bf16x3_swz_kernel<<<grid, 512, smem_bytes>>>(Q, K, V, bias, out);
}